// round 15
// baseline (speedup 1.0000x reference)
#include <cuda_runtime.h>
#include <math.h>

#define BB 64
#define NN 512
#define VV 64
#define HH 512
#define RR 4
#define KK 32
#define EPSF 1e-8f

// output offsets (floats), tuple order:
// logits, value, h_new, c_new, mem_new, w_r, write_w, usage_new, link_new, prec_new
#define OUT_LOGITS 0
#define OUT_VALUE  1152
#define OUT_H      1216
#define OUT_C      33984
#define OUT_MEM    66752
#define OUT_WR     2163904
#define OUT_WW     2294976
#define OUT_USAGE  2327744
#define OUT_LINK   2360512
#define OUT_PREC   19137728

// workspace
__device__ __align__(16) float g_rpi[BB * RR * 3];
__device__ __align__(16) float g_cw[BB * RR * NN];
__device__ __align__(16) float g_fw[BB * RR * NN];
__device__ __align__(16) float g_bwp[8 * BB * RR * NN];
__device__ __align__(16) float g_psi[BB * NN];
__device__ __align__(16) float g_inT[896 * BB];
__device__ __align__(16) float g_gpart[7 * BB * 2048];
__device__ __align__(16) float g_wo[BB * 256];
__device__ __align__(16) float g_erase[BB * VV];
__device__ __align__(16) float g_add[BB * VV];
__device__ __align__(16) float g_alloc[BB * NN];
__device__ int g_cnt;

__device__ __forceinline__ float sigf(float x) { return 1.f / (1.f + expf(-x)); }
__device__ __forceinline__ float softplusf(float x) { return x > 20.f ? x : log1pf(expf(x)); }
__device__ __forceinline__ unsigned f2o(float f) {
    unsigned u = __float_as_uint(f);
    return (u & 0x80000000u) ? ~u : (u | 0x80000000u);
}

// ============================================================
// 1) mega-kernel: content (256) | fwbw single-pass (512) | alloc (64)
// ============================================================
__global__ void __launch_bounds__(512) k_big(const float* __restrict__ mem,
                                             const float* __restrict__ link,
                                             const float* __restrict__ rw,
                                             const float* __restrict__ h,
                                             const float* __restrict__ Wr,
                                             const float* __restrict__ br,
                                             const float* __restrict__ usage) {
    __shared__ __align__(16) float buf[10240];   // tile[8192] | srw[2048]
    int tid = threadIdx.x;
    int blk = blockIdx.x;

    if (blk < 256) {
        // ---------------- content per (b,r): inline read-projection ----------------
        int b = blk >> 2, r = blk & 3;
        float* hsh  = buf;
        float* rosh = buf + 512;
        float* red  = buf + 580;
        float* sc   = buf + 596;
        int lane = tid & 31, warp = tid >> 5;

        hsh[tid] = h[b * 512 + tid];
        __syncthreads();

        for (int row = warp; row < 68; row += 16) {
            const float4* w4 = (const float4*)(Wr + (size_t)(r * 68 + row) * HH);
            float a = 0.f;
#pragma unroll
            for (int i = 0; i < 4; i++) {
                float4 w = w4[lane + 32 * i];
                float4 hv = *(const float4*)&hsh[(lane + 32 * i) * 4];
                a += w.x * hv.x + w.y * hv.y + w.z * hv.z + w.w * hv.w;
            }
#pragma unroll
            for (int o = 16; o > 0; o >>= 1) a += __shfl_down_sync(0xffffffffu, a, o);
            if (lane == 0) rosh[row] = a + br[r * 68 + row];
        }
        __syncthreads();

        if (tid == 0) {
            sc[0] = softplusf(rosh[64]);
            float p0 = rosh[65], p1 = rosh[66], p2 = rosh[67];
            float mx = fmaxf(p0, fmaxf(p1, p2));
            float e0 = expf(p0 - mx), e1 = expf(p1 - mx), e2 = expf(p2 - mx);
            float inv = 1.f / (e0 + e1 + e2);
            g_rpi[(b * 4 + r) * 3 + 0] = e0 * inv;
            g_rpi[(b * 4 + r) * 3 + 1] = e1 * inv;
            g_rpi[(b * 4 + r) * 3 + 2] = e2 * inv;
        }
        if (tid < 32) {
            float v = rosh[tid] * rosh[tid] + rosh[tid + 32] * rosh[tid + 32];
#pragma unroll
            for (int o = 16; o > 0; o >>= 1) v += __shfl_down_sync(0xffffffffu, v, o);
            if (tid == 0) sc[1] = fmaxf(sqrtf(v), EPSF);
        }
        __syncthreads();

        const float4* mrow = (const float4*)(mem + ((size_t)b * NN + tid) * VV);
        float acc = 0.f, nrm = 0.f;
#pragma unroll
        for (int i = 0; i < 16; i++) {
            float4 m4 = mrow[i];
            acc += m4.x * rosh[4 * i] + m4.y * rosh[4 * i + 1] + m4.z * rosh[4 * i + 2] + m4.w * rosh[4 * i + 3];
            nrm += m4.x * m4.x + m4.y * m4.y + m4.z * m4.z + m4.w * m4.w;
        }
        float score = sc[0] * acc / (fmaxf(sqrtf(nrm), EPSF) * sc[1]);
        unsigned u = f2o(score);

        unsigned prefix = 0u;
#pragma unroll
        for (int bit = 31; bit >= 0; --bit) {
            unsigned cand = prefix | (1u << bit);
            int cnt = __syncthreads_count(u >= cand);
            if (cnt >= KK) prefix = cand;
        }

        float e = (u >= prefix) ? expf(score) : 0.f;
        float v = e;
#pragma unroll
        for (int o = 16; o > 0; o >>= 1) v += __shfl_down_sync(0xffffffffu, v, o);
        if (lane == 0) red[warp] = v;
        __syncthreads();
        if (tid == 0) {
            float t = 0.f;
#pragma unroll
            for (int i = 0; i < 16; i++) t += red[i];
            sc[2] = t;
        }
        __syncthreads();
        g_cw[(b * 4 + r) * 512 + tid] = e / sc[2];
    } else if (blk < 768) {
        // ---------------- fw + bw single pass over row-chunk [mc*64, mc*64+64) ----
        int idx = blk - 256;
        int b = idx >> 3, mc = idx & 7;
        float* tile = buf;          // 16 x 512
        float* srw  = buf + 8192;   // 2048
        int lane = tid & 31, w = tid >> 5;

        ((float4*)srw)[tid] = ((const float4*)(rw + b * 2048))[tid];

        float a0 = 0.f, a1 = 0.f, a2 = 0.f, a3 = 0.f;
#pragma unroll
        for (int st = 0; st < 4; st++) {
            __syncthreads();
            const float4* src = (const float4*)(link + ((size_t)b * NN + mc * 64 + st * 16) * NN);
#pragma unroll
            for (int k = 0; k < 4; k++)
                ((float4*)tile)[tid + k * 512] = src[tid + k * 512];
            __syncthreads();

            float f0 = 0.f, f1 = 0.f, f2 = 0.f, f3 = 0.f;
#pragma unroll
            for (int i = 0; i < 4; i++) {
                int cq = lane + 32 * i;
                float4 l = *(const float4*)&tile[w * 512 + cq * 4];
                float4 w0 = *(const float4*)&srw[cq * 4];
                float4 w1 = *(const float4*)&srw[512 + cq * 4];
                float4 w2 = *(const float4*)&srw[1024 + cq * 4];
                float4 w3 = *(const float4*)&srw[1536 + cq * 4];
                f0 += l.x * w0.x + l.y * w0.y + l.z * w0.z + l.w * w0.w;
                f1 += l.x * w1.x + l.y * w1.y + l.z * w1.z + l.w * w1.w;
                f2 += l.x * w2.x + l.y * w2.y + l.z * w2.z + l.w * w2.w;
                f3 += l.x * w3.x + l.y * w3.y + l.z * w3.z + l.w * w3.w;
            }
#pragma unroll
            for (int o = 16; o > 0; o >>= 1) {
                f0 += __shfl_down_sync(0xffffffffu, f0, o);
                f1 += __shfl_down_sync(0xffffffffu, f1, o);
                f2 += __shfl_down_sync(0xffffffffu, f2, o);
                f3 += __shfl_down_sync(0xffffffffu, f3, o);
            }
            if (lane == 0) {
                int n = mc * 64 + st * 16 + w;
                g_fw[(b * 4 + 0) * 512 + n] = f0;
                g_fw[(b * 4 + 1) * 512 + n] = f1;
                g_fw[(b * 4 + 2) * 512 + n] = f2;
                g_fw[(b * 4 + 3) * 512 + n] = f3;
            }

#pragma unroll
            for (int m = 0; m < 16; m++) {
                float l = tile[m * 512 + tid];
                int gm = mc * 64 + st * 16 + m;
                a0 += l * srw[gm];
                a1 += l * srw[512 + gm];
                a2 += l * srw[1024 + gm];
                a3 += l * srw[1536 + gm];
            }
        }
        size_t base = (((size_t)mc * 64 + b) * 4) * 512 + tid;
        g_bwp[base]        = a0;
        g_bwp[base + 512]  = a1;
        g_bwp[base + 1024] = a2;
        g_bwp[base + 1536] = a3;
    } else {
        // ---------------- allocation per b ----------
        int b = blk - 768;
        buf[tid] = usage[b * 512 + tid];
        __syncthreads();
        float un = buf[tid];
        float prod = 1.f;
#pragma unroll 8
        for (int m = 0; m < 512; m++) {
            float um = buf[m];
            bool before = (um < un) || (um == un && m < tid);
            prod *= before ? um : 1.f;
        }
        g_alloc[b * 512 + tid] = (1.f - un) * prod;
    }
}

// ============================================================
// 2) fused per-b: w_r mix + psi + rvec + pack inT
// ============================================================
__global__ void __launch_bounds__(512) k_mix(const float* __restrict__ mem,
                                             const float* __restrict__ x,
                                             const float* __restrict__ h,
                                             float* __restrict__ out) {
    int b = blockIdx.x, tid = threadIdx.x;
    __shared__ float swr[4][512];
    __shared__ float sred[512];
    __shared__ float srv[256];
    int n = tid;
    float psi = 1.f;
#pragma unroll
    for (int r = 0; r < 4; r++) {
        int o = (b * 4 + r) * 512 + n;
        float bwv = 0.f;
#pragma unroll
        for (int mc = 0; mc < 8; mc++)
            bwv += g_bwp[((size_t)(mc * 64 + b) * 4 + r) * 512 + n];
        float p0 = g_rpi[(b * 4 + r) * 3 + 0];
        float p1 = g_rpi[(b * 4 + r) * 3 + 1];
        float p2 = g_rpi[(b * 4 + r) * 3 + 2];
        float wr = p0 * bwv + p1 * g_cw[o] + p2 * g_fw[o];
        swr[r][n] = wr;
        out[OUT_WR + o] = wr;
        psi *= (1.f - wr);
    }
    g_psi[b * 512 + n] = psi;
    __syncthreads();

    int half = tid >> 8;
    int r = (tid >> 6) & 3;
    int v = tid & 63;
    const float* mp = mem + (size_t)b * NN * VV + v;
    float acc = 0.f;
#pragma unroll 4
    for (int nn = half * 256; nn < half * 256 + 256; nn++)
        acc += swr[r][nn] * mp[(size_t)nn * 64];
    sred[tid] = acc;
    __syncthreads();
    if (tid < 256) srv[tid] = sred[tid] + sred[tid + 256];
    __syncthreads();

    for (int k = tid; k < 896; k += 512) {
        float val;
        if (k < 128) val = x[b * 128 + k];
        else if (k < 384) val = srv[k - 128];
        else val = h[b * 512 + (k - 384)];
        g_inT[k * 64 + b] = val;
    }
}

// ============================================================
// 3) gates GEMM: (64b x 2048j), K=896 = 7 splits of 128; j-tile 32
// ============================================================
__global__ void __launch_bounds__(256) k_gates(const float* __restrict__ Wih,
                                               const float* __restrict__ Whh) {
    __shared__ __align__(16) float Wt[32][34];
    __shared__ __align__(16) float It[32][68];
    int tid = threadIdx.x;
    int ks = blockIdx.y;
    int koff = ks * 128;
    int j0 = blockIdx.x * 32;
    int tx = tid & 15, ty = tid >> 4;
    int jj = tid >> 3, kq = tid & 7;
    float acc[2][4];
#pragma unroll
    for (int i = 0; i < 2; i++)
#pragma unroll
        for (int j = 0; j < 4; j++) acc[i][j] = 0.f;

    for (int kst = 0; kst < 128; kst += 32) {
        int vk = koff + kst + kq * 4;
        const float* wp = (vk < 384) ? (Wih + (size_t)(j0 + jj) * 384 + vk)
                                     : (Whh + (size_t)(j0 + jj) * 512 + (vk - 384));
        float4 wv = *(const float4*)wp;
        Wt[kq * 4 + 0][jj] = wv.x;
        Wt[kq * 4 + 1][jj] = wv.y;
        Wt[kq * 4 + 2][jj] = wv.z;
        Wt[kq * 4 + 3][jj] = wv.w;
        *(float4*)&It[ty][tx * 4]      = *(const float4*)&g_inT[(koff + kst + ty) * 64 + tx * 4];
        *(float4*)&It[ty + 16][tx * 4] = *(const float4*)&g_inT[(koff + kst + ty + 16) * 64 + tx * 4];
        __syncthreads();
#pragma unroll
        for (int kk = 0; kk < 32; kk++) {
            float4 av = *(float4*)&It[kk][tx * 4];
            float2 wv2 = *(float2*)&Wt[kk][ty * 2];
            acc[0][0] += wv2.x * av.x; acc[0][1] += wv2.x * av.y; acc[0][2] += wv2.x * av.z; acc[0][3] += wv2.x * av.w;
            acc[1][0] += wv2.y * av.x; acc[1][1] += wv2.y * av.y; acc[1][2] += wv2.y * av.z; acc[1][3] += wv2.y * av.w;
        }
        __syncthreads();
    }
#pragma unroll
    for (int jq = 0; jq < 2; jq++)
#pragma unroll
        for (int bq = 0; bq < 4; bq++)
            g_gpart[(((size_t)ks * 64 + (tx * 4 + bq)) * 2048) + j0 + ty * 2 + jq] = acc[jq][bq];
}

// ============================================================
// 4) LSTM + projections, parallel over (b, 7 row-chunks); zeroes tail flag
// ============================================================
__global__ void __launch_bounds__(512) k_hout(
    const float* __restrict__ c, const float* __restrict__ bih, const float* __restrict__ bhh,
    const float* __restrict__ Ww, const float* __restrict__ bw_,
    const float* __restrict__ Wp, const float* __restrict__ bp,
    const float* __restrict__ Wv, const float* __restrict__ bv,
    float* __restrict__ out) {
    int b = blockIdx.x, pc = blockIdx.y, tid = threadIdx.x;
    __shared__ __align__(16) float sh[512];
    int lane = tid & 31, wid = tid >> 5;

    if (b == 0 && pc == 0 && tid == 0) g_cnt = 0;   // reset tail flag each launch

    float gi = bih[tid] + bhh[tid];
    float gf = bih[512 + tid] + bhh[512 + tid];
    float gg = bih[1024 + tid] + bhh[1024 + tid];
    float go = bih[1536 + tid] + bhh[1536 + tid];
#pragma unroll
    for (int ks = 0; ks < 7; ks++) {
        const float* gp = g_gpart + ((size_t)(ks * 64 + b) * 2048);
        gi += gp[tid];
        gf += gp[512 + tid];
        gg += gp[1024 + tid];
        go += gp[1536 + tid];
    }
    float cn = sigf(gf) * c[b * 512 + tid] + sigf(gi) * tanhf(gg);
    float hn = sigf(go) * tanhf(cn);
    if (pc == 0) {
        out[OUT_C + b * 512 + tid] = cn;
        out[OUT_H + b * 512 + tid] = hn;
    }
    sh[tid] = hn;
    __syncthreads();

#pragma unroll
    for (int rr = 0; rr < 2; rr++) {
        int ro = wid + rr * 16;
        int row = pc * 31 + ro;
        if (ro < 31 && row < 214) {
            const float* wrow;
            float bias;
            if (row < 195)      { wrow = Ww + row * 512;         bias = bw_[row]; }
            else if (row < 213) { wrow = Wp + (row - 195) * 512; bias = bp[row - 195]; }
            else                { wrow = Wv;                     bias = bv[0]; }
            const float4* w4 = (const float4*)wrow;
            float acc = 0.f;
#pragma unroll
            for (int i = 0; i < 4; i++) {
                float4 wv = w4[lane + 32 * i];
                float4 hv = *(const float4*)&sh[(lane + 32 * i) * 4];
                acc += wv.x * hv.x + wv.y * hv.y + wv.z * hv.z + wv.w * hv.w;
            }
#pragma unroll
            for (int o = 16; o > 0; o >>= 1) acc += __shfl_down_sync(0xffffffffu, acc, o);
            if (lane == 0) {
                acc += bias;
                if (row < 64)       g_wo[b * 256 + row] = acc;
                else if (row < 128) g_erase[b * 64 + (row - 64)] = sigf(acc);
                else if (row < 192) g_add[b * 64 + (row - 128)] = tanhf(acc);
                else if (row < 195) g_wo[b * 256 + row] = acc;
                else if (row < 213) out[OUT_LOGITS + b * 18 + (row - 195)] = acc;
                else                out[OUT_VALUE + b] = acc;
            }
        }
    }
}

// ============================================================
// 5) fused tail: wall (64 blocks) | mem update (2048) | link update (2048)
//    consumers spin on g_cnt (producers always in wave 1: lowest bids)
// ============================================================
__global__ void __launch_bounds__(256) k_tail(const float* __restrict__ mem,
                                              const float* __restrict__ usage,
                                              const float* __restrict__ wwin,
                                              const float* __restrict__ prec,
                                              const float* __restrict__ link,
                                              float* __restrict__ out) {
    int bx = blockIdx.x;
    int tid = threadIdx.x;

    if (bx < 64) {
        // ---------------- wall: per-b write path (2 n per thread) ----------------
        int b = bx;
        __shared__ __align__(16) float skey[64];
        __shared__ float red[8];
        __shared__ float part[2];
        __shared__ float s_beta, s_knorm, s_ga, s_gw, s_m, s_sum, s_ws;
        int lane = tid & 31, wid = tid >> 5;

        if (tid < 64) {
            float kv = g_wo[b * 256 + tid];
            skey[tid] = kv;
            float s = kv * kv;
#pragma unroll
            for (int o = 16; o > 0; o >>= 1) s += __shfl_down_sync(0xffffffffu, s, o);
            if (lane == 0) part[tid >> 5] = s;
        }
        __syncthreads();
        if (tid == 0) {
            s_knorm = fmaxf(sqrtf(part[0] + part[1]), EPSF);
            s_beta = softplusf(g_wo[b * 256 + 192]);
            s_ga = sigf(g_wo[b * 256 + 193]);
            s_gw = sigf(g_wo[b * 256 + 194]);
        }
        __syncthreads();

        float sim[2];
#pragma unroll
        for (int q = 0; q < 2; q++) {
            int n = tid + q * 256;
            const float4* mrow = (const float4*)(mem + ((size_t)b * NN + n) * VV);
            float acc = 0.f, nrm = 0.f;
#pragma unroll
            for (int i = 0; i < 16; i++) {
                float4 m4 = mrow[i];
                acc += m4.x * skey[4 * i] + m4.y * skey[4 * i + 1] + m4.z * skey[4 * i + 2] + m4.w * skey[4 * i + 3];
                nrm += m4.x * m4.x + m4.y * m4.y + m4.z * m4.z + m4.w * m4.w;
            }
            sim[q] = s_beta * acc / (fmaxf(sqrtf(nrm), EPSF) * s_knorm);
        }

        float v = fmaxf(sim[0], sim[1]);
#pragma unroll
        for (int o = 16; o > 0; o >>= 1) v = fmaxf(v, __shfl_down_sync(0xffffffffu, v, o));
        if (lane == 0) red[wid] = v;
        __syncthreads();
        if (tid == 0) {
            float m = red[0];
#pragma unroll
            for (int i = 1; i < 8; i++) m = fmaxf(m, red[i]);
            s_m = m;
        }
        __syncthreads();
        float e0 = expf(sim[0] - s_m), e1 = expf(sim[1] - s_m);
        v = e0 + e1;
#pragma unroll
        for (int o = 16; o > 0; o >>= 1) v += __shfl_down_sync(0xffffffffu, v, o);
        if (lane == 0) red[wid] = v;
        __syncthreads();
        if (tid == 0) {
            float t = 0.f;
#pragma unroll
            for (int i = 0; i < 8; i++) t += red[i];
            s_sum = t;
        }
        __syncthreads();

        float ww0 = s_gw * (s_ga * g_alloc[b * 512 + tid]       + (1.f - s_ga) * (e0 / s_sum));
        float ww1 = s_gw * (s_ga * g_alloc[b * 512 + tid + 256] + (1.f - s_ga) * (e1 / s_sum));
        out[OUT_WW + b * 512 + tid]       = ww0;
        out[OUT_WW + b * 512 + tid + 256] = ww1;
        v = ww0 + ww1;
#pragma unroll
        for (int o = 16; o > 0; o >>= 1) v += __shfl_down_sync(0xffffffffu, v, o);
        if (lane == 0) red[wid] = v;
        __syncthreads();
        if (tid == 0) {
            float t = 0.f;
#pragma unroll
            for (int i = 0; i < 8; i++) t += red[i];
            s_ws = t;
        }
        __syncthreads();
#pragma unroll
        for (int q = 0; q < 2; q++) {
            int n = tid + q * 256;
            float ww = q ? ww1 : ww0;
            out[OUT_PREC + b * 512 + n] = (1.f - s_ws) * prec[b * 512 + n] + ww;
            float u = usage[b * 512 + n], w0 = wwin[b * 512 + n];
            out[OUT_USAGE + b * 512 + n] = (u + w0 - u * w0) * g_psi[b * 512 + n];
        }
        __threadfence();
        __syncthreads();
        if (tid == 0) atomicAdd(&g_cnt, 1);
    } else if (bx < 2112) {
        // ---------------- memory update ----------------
        int gid = (bx - 64) * 256 + tid;
        int v4 = gid & 15, n = (gid >> 4) & 511, b = gid >> 13;
        float4 m = ((const float4*)mem)[gid];            // prologue under spin
        float4 er = ((const float4*)g_erase)[b * 16 + v4];
        float4 ad = ((const float4*)g_add)[b * 16 + v4];
        if (tid == 0) {
            while (atomicAdd(&g_cnt, 0) < 64) __nanosleep(64);
        }
        __syncthreads();
        __threadfence();
        float ww = out[OUT_WW + b * 512 + n];
        float4 r;
        r.x = m.x * (1.f - ww * er.x) + ww * ad.x;
        r.y = m.y * (1.f - ww * er.y) + ww * ad.y;
        r.z = m.z * (1.f - ww * er.z) + ww * ad.z;
        r.w = m.w * (1.f - ww * er.w) + ww * ad.w;
        __stwt(&((float4*)(out + OUT_MEM))[gid], r);
    } else {
        // ---------------- link update: tile of 16 n rows ----------------
        int idx = bx - 2112;
        int b = idx >> 5;
        int nt = idx & 31;
        int n0 = nt * 16;
        __shared__ __align__(16) float swm[512];
        __shared__ __align__(16) float spp[512];
        __shared__ float sww[16];
        if (tid >= 128)
            ((float4*)spp)[tid - 128] = ((const float4*)(prec + b * 512))[tid - 128];
        if (tid == 0) {
            while (atomicAdd(&g_cnt, 0) < 64) __nanosleep(64);
        }
        __syncthreads();
        __threadfence();
        if (tid < 128)
            ((float4*)swm)[tid] = ((const float4*)(out + OUT_WW + b * 512))[tid];
        if (tid < 16) sww[tid] = out[OUT_WW + b * 512 + n0 + tid];
        __syncthreads();

        int mq = tid & 127;
        int nh = tid >> 7;
        int m0 = mq * 4;
        const float4* lbase = (const float4*)(link + (size_t)b * NN * NN);
        float4* obase = (float4*)(out + OUT_LINK + (size_t)b * NN * NN);
        float4 wm = *(const float4*)&swm[m0];
        float4 p  = *(const float4*)&spp[m0];
        float4 omm;
        omm.x = 1.f - wm.x; omm.y = 1.f - wm.y; omm.z = 1.f - wm.z; omm.w = 1.f - wm.w;
#pragma unroll
        for (int i = 0; i < 8; i++) {
            int n = n0 + i * 2 + nh;
            float wn = sww[i * 2 + nh];
            float om = 1.f - wn;
            float4 l = lbase[(size_t)n * 128 + mq];
            float4 r;
            r.x = om * omm.x * l.x + wn * p.x;
            r.y = om * omm.y * l.y + wn * p.y;
            r.z = om * omm.z * l.z + wn * p.z;
            r.w = om * omm.w * l.w + wn * p.w;
            if (m0 == n)     r.x = 0.f;
            if (m0 + 1 == n) r.y = 0.f;
            if (m0 + 2 == n) r.z = 0.f;
            if (m0 + 3 == n) r.w = 0.f;
            __stwt(&obase[(size_t)n * 128 + mq], r);
        }
    }
}

extern "C" void kernel_launch(void* const* d_in, const int* in_sizes, int n_in,
                              void* d_out, int out_size) {
    const float* x             = (const float*)d_in[0];
    const float* h             = (const float*)d_in[1];
    const float* c             = (const float*)d_in[2];
    const float* memory        = (const float*)d_in[3];
    const float* read_weights  = (const float*)d_in[4];
    const float* write_weights = (const float*)d_in[5];
    const float* usage         = (const float*)d_in[6];
    const float* link          = (const float*)d_in[7];
    const float* prec          = (const float*)d_in[8];
    const float* W_ih          = (const float*)d_in[9];
    const float* W_hh          = (const float*)d_in[10];
    const float* b_ih          = (const float*)d_in[11];
    const float* b_hh          = (const float*)d_in[12];
    const float* W_read        = (const float*)d_in[13];
    const float* b_read        = (const float*)d_in[14];
    const float* W_write       = (const float*)d_in[15];
    const float* b_write       = (const float*)d_in[16];
    const float* W_pol         = (const float*)d_in[17];
    const float* b_pol         = (const float*)d_in[18];
    const float* W_val         = (const float*)d_in[19];
    const float* b_val         = (const float*)d_in[20];
    float* out = (float*)d_out;

    k_big<<<832, 512>>>(memory, link, read_weights, h, W_read, b_read, usage);
    k_mix<<<64, 512>>>(memory, x, h, out);
    k_gates<<<dim3(64, 7), 256>>>(W_ih, W_hh);
    k_hout<<<dim3(64, 7), 512>>>(c, b_ih, b_hh, W_write, b_write, W_pol, b_pol, W_val, b_val, out);
    k_tail<<<4160, 256>>>(memory, usage, write_weights, prec, link, out);
}

// round 16
// speedup vs baseline: 1.0890x; 1.0890x over previous
#include <cuda_runtime.h>
#include <math.h>

#define BB 64
#define NN 512
#define VV 64
#define HH 512
#define RR 4
#define KK 32
#define EPSF 1e-8f

// output offsets (floats), tuple order:
// logits, value, h_new, c_new, mem_new, w_r, write_w, usage_new, link_new, prec_new
#define OUT_LOGITS 0
#define OUT_VALUE  1152
#define OUT_H      1216
#define OUT_C      33984
#define OUT_MEM    66752
#define OUT_WR     2163904
#define OUT_WW     2294976
#define OUT_USAGE  2327744
#define OUT_LINK   2360512
#define OUT_PREC   19137728

// workspace
__device__ __align__(16) float g_rpi[BB * RR * 3];
__device__ __align__(16) float g_cw[BB * RR * NN];
__device__ __align__(16) float g_fw[BB * RR * NN];
__device__ __align__(16) float g_bwp[8 * BB * RR * NN];
__device__ __align__(16) float g_psi[BB * NN];
__device__ __align__(16) float g_inT[896 * BB];
__device__ __align__(16) float g_gpart[7 * BB * 2048];
__device__ __align__(16) float g_wo[BB * 256];
__device__ __align__(16) float g_erase[BB * VV];
__device__ __align__(16) float g_add[BB * VV];
__device__ __align__(16) float g_alloc[BB * NN];

__device__ __forceinline__ float sigf(float x) { return 1.f / (1.f + expf(-x)); }
__device__ __forceinline__ float softplusf(float x) { return x > 20.f ? x : log1pf(expf(x)); }
__device__ __forceinline__ unsigned f2o(float f) {
    unsigned u = __float_as_uint(f);
    return (u & 0x80000000u) ? ~u : (u | 0x80000000u);
}

// ============================================================
// 1) mega-kernel: content (256) | fwbw single-pass pipelined (512) | alloc (64)
// ============================================================
__global__ void __launch_bounds__(512) k_big(const float* __restrict__ mem,
                                             const float* __restrict__ link,
                                             const float* __restrict__ rw,
                                             const float* __restrict__ h,
                                             const float* __restrict__ Wr,
                                             const float* __restrict__ br,
                                             const float* __restrict__ usage) {
    __shared__ __align__(16) float buf[10240];   // tile[8192] | srw[2048]
    int tid = threadIdx.x;
    int blk = blockIdx.x;

    if (blk < 256) {
        // ---------------- content per (b,r): inline read-projection ----------------
        int b = blk >> 2, r = blk & 3;
        float* hsh  = buf;
        float* rosh = buf + 512;
        float* red  = buf + 580;
        float* sc   = buf + 596;
        int lane = tid & 31, warp = tid >> 5;

        hsh[tid] = h[b * 512 + tid];
        __syncthreads();

        for (int row = warp; row < 68; row += 16) {
            const float4* w4 = (const float4*)(Wr + (size_t)(r * 68 + row) * HH);
            float a = 0.f;
#pragma unroll
            for (int i = 0; i < 4; i++) {
                float4 w = w4[lane + 32 * i];
                float4 hv = *(const float4*)&hsh[(lane + 32 * i) * 4];
                a += w.x * hv.x + w.y * hv.y + w.z * hv.z + w.w * hv.w;
            }
#pragma unroll
            for (int o = 16; o > 0; o >>= 1) a += __shfl_down_sync(0xffffffffu, a, o);
            if (lane == 0) rosh[row] = a + br[r * 68 + row];
        }
        __syncthreads();

        if (tid == 0) {
            sc[0] = softplusf(rosh[64]);
            float p0 = rosh[65], p1 = rosh[66], p2 = rosh[67];
            float mx = fmaxf(p0, fmaxf(p1, p2));
            float e0 = expf(p0 - mx), e1 = expf(p1 - mx), e2 = expf(p2 - mx);
            float inv = 1.f / (e0 + e1 + e2);
            g_rpi[(b * 4 + r) * 3 + 0] = e0 * inv;
            g_rpi[(b * 4 + r) * 3 + 1] = e1 * inv;
            g_rpi[(b * 4 + r) * 3 + 2] = e2 * inv;
        }
        if (tid < 32) {
            float v = rosh[tid] * rosh[tid] + rosh[tid + 32] * rosh[tid + 32];
#pragma unroll
            for (int o = 16; o > 0; o >>= 1) v += __shfl_down_sync(0xffffffffu, v, o);
            if (tid == 0) sc[1] = fmaxf(sqrtf(v), EPSF);
        }
        __syncthreads();

        const float4* mrow = (const float4*)(mem + ((size_t)b * NN + tid) * VV);
        float acc = 0.f, nrm = 0.f;
#pragma unroll
        for (int i = 0; i < 16; i++) {
            float4 m4 = mrow[i];
            acc += m4.x * rosh[4 * i] + m4.y * rosh[4 * i + 1] + m4.z * rosh[4 * i + 2] + m4.w * rosh[4 * i + 3];
            nrm += m4.x * m4.x + m4.y * m4.y + m4.z * m4.z + m4.w * m4.w;
        }
        float score = sc[0] * acc / (fmaxf(sqrtf(nrm), EPSF) * sc[1]);
        unsigned u = f2o(score);

        unsigned prefix = 0u;
#pragma unroll
        for (int bit = 31; bit >= 0; --bit) {
            unsigned cand = prefix | (1u << bit);
            int cnt = __syncthreads_count(u >= cand);
            if (cnt >= KK) prefix = cand;
        }

        float e = (u >= prefix) ? expf(score) : 0.f;
        float v = e;
#pragma unroll
        for (int o = 16; o > 0; o >>= 1) v += __shfl_down_sync(0xffffffffu, v, o);
        if (lane == 0) red[warp] = v;
        __syncthreads();
        if (tid == 0) {
            float t = 0.f;
#pragma unroll
            for (int i = 0; i < 16; i++) t += red[i];
            sc[2] = t;
        }
        __syncthreads();
        g_cw[(b * 4 + r) * 512 + tid] = e / sc[2];
    } else if (blk < 768) {
        // ---------------- fw + bw single pass, software-pipelined loads ----------
        int idx = blk - 256;
        int b = idx >> 3, mc = idx & 7;
        float* tile = buf;          // 16 x 512
        float* srw  = buf + 8192;   // 2048
        int lane = tid & 31, w = tid >> 5;

        ((float4*)srw)[tid] = ((const float4*)(rw + b * 2048))[tid];

        // preload stage 0
        const float4* src0 = (const float4*)(link + ((size_t)b * NN + mc * 64) * NN);
        float4 p0 = src0[tid], p1 = src0[tid + 512], p2 = src0[tid + 1024], p3 = src0[tid + 1536];

        float a0 = 0.f, a1 = 0.f, a2 = 0.f, a3 = 0.f;   // bw accum, col = tid
#pragma unroll
        for (int st = 0; st < 4; st++) {
            // deposit current stage to smem
            ((float4*)tile)[tid]        = p0;
            ((float4*)tile)[tid + 512]  = p1;
            ((float4*)tile)[tid + 1024] = p2;
            ((float4*)tile)[tid + 1536] = p3;
            __syncthreads();

            // issue next stage's loads (overlap with compute below)
            if (st < 3) {
                const float4* src = (const float4*)(link + ((size_t)b * NN + mc * 64 + (st + 1) * 16) * NN);
                p0 = src[tid]; p1 = src[tid + 512]; p2 = src[tid + 1024]; p3 = src[tid + 1536];
            }

            // fw: warp w handles row w of sub-tile -> n = mc*64 + st*16 + w
            float f0 = 0.f, f1 = 0.f, f2 = 0.f, f3 = 0.f;
#pragma unroll
            for (int i = 0; i < 4; i++) {
                int cq = lane + 32 * i;
                float4 l = *(const float4*)&tile[w * 512 + cq * 4];
                float4 w0 = *(const float4*)&srw[cq * 4];
                float4 w1 = *(const float4*)&srw[512 + cq * 4];
                float4 w2 = *(const float4*)&srw[1024 + cq * 4];
                float4 w3 = *(const float4*)&srw[1536 + cq * 4];
                f0 += l.x * w0.x + l.y * w0.y + l.z * w0.z + l.w * w0.w;
                f1 += l.x * w1.x + l.y * w1.y + l.z * w1.z + l.w * w1.w;
                f2 += l.x * w2.x + l.y * w2.y + l.z * w2.z + l.w * w2.w;
                f3 += l.x * w3.x + l.y * w3.y + l.z * w3.z + l.w * w3.w;
            }
#pragma unroll
            for (int o = 16; o > 0; o >>= 1) {
                f0 += __shfl_down_sync(0xffffffffu, f0, o);
                f1 += __shfl_down_sync(0xffffffffu, f1, o);
                f2 += __shfl_down_sync(0xffffffffu, f2, o);
                f3 += __shfl_down_sync(0xffffffffu, f3, o);
            }
            if (lane == 0) {
                int n = mc * 64 + st * 16 + w;
                g_fw[(b * 4 + 0) * 512 + n] = f0;
                g_fw[(b * 4 + 1) * 512 + n] = f1;
                g_fw[(b * 4 + 2) * 512 + n] = f2;
                g_fw[(b * 4 + 3) * 512 + n] = f3;
            }

            // bw partial: col = tid, rows of sub-tile are m
#pragma unroll
            for (int m = 0; m < 16; m++) {
                float l = tile[m * 512 + tid];
                int gm = mc * 64 + st * 16 + m;
                a0 += l * srw[gm];
                a1 += l * srw[512 + gm];
                a2 += l * srw[1024 + gm];
                a3 += l * srw[1536 + gm];
            }
            __syncthreads();
        }
        size_t base = (((size_t)mc * 64 + b) * 4) * 512 + tid;
        g_bwp[base]        = a0;
        g_bwp[base + 512]  = a1;
        g_bwp[base + 1024] = a2;
        g_bwp[base + 1536] = a3;
    } else {
        // ---------------- allocation per b: barrier-free selection product ----------
        int b = blk - 768;
        buf[tid] = usage[b * 512 + tid];
        __syncthreads();
        float un = buf[tid];
        float prod = 1.f;
#pragma unroll 8
        for (int m = 0; m < 512; m++) {
            float um = buf[m];
            bool before = (um < un) || (um == un && m < tid);
            prod *= before ? um : 1.f;
        }
        g_alloc[b * 512 + tid] = (1.f - un) * prod;
    }
}

// ============================================================
// 2) fused per-b: w_r mix + psi + rvec + pack inT
// ============================================================
__global__ void __launch_bounds__(512) k_mix(const float* __restrict__ mem,
                                             const float* __restrict__ x,
                                             const float* __restrict__ h,
                                             float* __restrict__ out) {
    int b = blockIdx.x, tid = threadIdx.x;
    __shared__ float swr[4][512];
    __shared__ float sred[512];
    __shared__ float srv[256];
    int n = tid;
    float psi = 1.f;
#pragma unroll
    for (int r = 0; r < 4; r++) {
        int o = (b * 4 + r) * 512 + n;
        float bwv = 0.f;
#pragma unroll
        for (int mc = 0; mc < 8; mc++)
            bwv += g_bwp[((size_t)(mc * 64 + b) * 4 + r) * 512 + n];
        float p0 = g_rpi[(b * 4 + r) * 3 + 0];
        float p1 = g_rpi[(b * 4 + r) * 3 + 1];
        float p2 = g_rpi[(b * 4 + r) * 3 + 2];
        float wr = p0 * bwv + p1 * g_cw[o] + p2 * g_fw[o];
        swr[r][n] = wr;
        out[OUT_WR + o] = wr;
        psi *= (1.f - wr);
    }
    g_psi[b * 512 + n] = psi;
    __syncthreads();

    int half = tid >> 8;
    int r = (tid >> 6) & 3;
    int v = tid & 63;
    const float* mp = mem + (size_t)b * NN * VV + v;
    float acc = 0.f;
#pragma unroll 4
    for (int nn = half * 256; nn < half * 256 + 256; nn++)
        acc += swr[r][nn] * mp[(size_t)nn * 64];
    sred[tid] = acc;
    __syncthreads();
    if (tid < 256) srv[tid] = sred[tid] + sred[tid + 256];
    __syncthreads();

    for (int k = tid; k < 896; k += 512) {
        float val;
        if (k < 128) val = x[b * 128 + k];
        else if (k < 384) val = srv[k - 128];
        else val = h[b * 512 + (k - 384)];
        g_inT[k * 64 + b] = val;
    }
}

// ============================================================
// 3) gates GEMM: (64b x 2048j), K=896 = 7 splits of 128; j-tile 32
// ============================================================
__global__ void __launch_bounds__(256) k_gates(const float* __restrict__ Wih,
                                               const float* __restrict__ Whh) {
    __shared__ __align__(16) float Wt[32][34];
    __shared__ __align__(16) float It[32][68];
    int tid = threadIdx.x;
    int ks = blockIdx.y;
    int koff = ks * 128;
    int j0 = blockIdx.x * 32;
    int tx = tid & 15, ty = tid >> 4;
    int jj = tid >> 3, kq = tid & 7;
    float acc[2][4];
#pragma unroll
    for (int i = 0; i < 2; i++)
#pragma unroll
        for (int j = 0; j < 4; j++) acc[i][j] = 0.f;

    for (int kst = 0; kst < 128; kst += 32) {
        int vk = koff + kst + kq * 4;
        const float* wp = (vk < 384) ? (Wih + (size_t)(j0 + jj) * 384 + vk)
                                     : (Whh + (size_t)(j0 + jj) * 512 + (vk - 384));
        float4 wv = *(const float4*)wp;
        Wt[kq * 4 + 0][jj] = wv.x;
        Wt[kq * 4 + 1][jj] = wv.y;
        Wt[kq * 4 + 2][jj] = wv.z;
        Wt[kq * 4 + 3][jj] = wv.w;
        *(float4*)&It[ty][tx * 4]      = *(const float4*)&g_inT[(koff + kst + ty) * 64 + tx * 4];
        *(float4*)&It[ty + 16][tx * 4] = *(const float4*)&g_inT[(koff + kst + ty + 16) * 64 + tx * 4];
        __syncthreads();
#pragma unroll
        for (int kk = 0; kk < 32; kk++) {
            float4 av = *(float4*)&It[kk][tx * 4];
            float2 wv2 = *(float2*)&Wt[kk][ty * 2];
            acc[0][0] += wv2.x * av.x; acc[0][1] += wv2.x * av.y; acc[0][2] += wv2.x * av.z; acc[0][3] += wv2.x * av.w;
            acc[1][0] += wv2.y * av.x; acc[1][1] += wv2.y * av.y; acc[1][2] += wv2.y * av.z; acc[1][3] += wv2.y * av.w;
        }
        __syncthreads();
    }
#pragma unroll
    for (int jq = 0; jq < 2; jq++)
#pragma unroll
        for (int bq = 0; bq < 4; bq++)
            g_gpart[(((size_t)ks * 64 + (tx * 4 + bq)) * 2048) + j0 + ty * 2 + jq] = acc[jq][bq];
}

// ============================================================
// 4) LSTM + projections, parallel over (b, 7 row-chunks)
// ============================================================
__global__ void __launch_bounds__(512) k_hout(
    const float* __restrict__ c, const float* __restrict__ bih, const float* __restrict__ bhh,
    const float* __restrict__ Ww, const float* __restrict__ bw_,
    const float* __restrict__ Wp, const float* __restrict__ bp,
    const float* __restrict__ Wv, const float* __restrict__ bv,
    float* __restrict__ out) {
    int b = blockIdx.x, pc = blockIdx.y, tid = threadIdx.x;
    __shared__ __align__(16) float sh[512];
    int lane = tid & 31, wid = tid >> 5;

    float gi = bih[tid] + bhh[tid];
    float gf = bih[512 + tid] + bhh[512 + tid];
    float gg = bih[1024 + tid] + bhh[1024 + tid];
    float go = bih[1536 + tid] + bhh[1536 + tid];
#pragma unroll
    for (int ks = 0; ks < 7; ks++) {
        const float* gp = g_gpart + ((size_t)(ks * 64 + b) * 2048);
        gi += gp[tid];
        gf += gp[512 + tid];
        gg += gp[1024 + tid];
        go += gp[1536 + tid];
    }
    float cn = sigf(gf) * c[b * 512 + tid] + sigf(gi) * tanhf(gg);
    float hn = sigf(go) * tanhf(cn);
    if (pc == 0) {
        out[OUT_C + b * 512 + tid] = cn;
        out[OUT_H + b * 512 + tid] = hn;
    }
    sh[tid] = hn;
    __syncthreads();

#pragma unroll
    for (int rr = 0; rr < 2; rr++) {
        int ro = wid + rr * 16;
        int row = pc * 31 + ro;
        if (ro < 31 && row < 214) {
            const float* wrow;
            float bias;
            if (row < 195)      { wrow = Ww + row * 512;         bias = bw_[row]; }
            else if (row < 213) { wrow = Wp + (row - 195) * 512; bias = bp[row - 195]; }
            else                { wrow = Wv;                     bias = bv[0]; }
            const float4* w4 = (const float4*)wrow;
            float acc = 0.f;
#pragma unroll
            for (int i = 0; i < 4; i++) {
                float4 wv = w4[lane + 32 * i];
                float4 hv = *(const float4*)&sh[(lane + 32 * i) * 4];
                acc += wv.x * hv.x + wv.y * hv.y + wv.z * hv.z + wv.w * hv.w;
            }
#pragma unroll
            for (int o = 16; o > 0; o >>= 1) acc += __shfl_down_sync(0xffffffffu, acc, o);
            if (lane == 0) {
                acc += bias;
                if (row < 64)       g_wo[b * 256 + row] = acc;
                else if (row < 128) g_erase[b * 64 + (row - 64)] = sigf(acc);
                else if (row < 192) g_add[b * 64 + (row - 128)] = tanhf(acc);
                else if (row < 195) g_wo[b * 256 + row] = acc;
                else if (row < 213) out[OUT_LOGITS + b * 18 + (row - 195)] = acc;
                else                out[OUT_VALUE + b] = acc;
            }
        }
    }
}

// ============================================================
// 5) per-b write path (short)
// ============================================================
__global__ void __launch_bounds__(512) k_wall(
    const float* __restrict__ mem, const float* __restrict__ usage,
    const float* __restrict__ wwin, const float* __restrict__ prec,
    float* __restrict__ out) {
    int b = blockIdx.x, tid = threadIdx.x;
    __shared__ __align__(16) float skey[64];
    __shared__ float red[16];
    __shared__ float part[2];
    __shared__ float s_beta, s_knorm, s_ga, s_gw, s_m, s_sum, s_ws;
    int lane = tid & 31, wid = tid >> 5;

    if (tid < 64) {
        float kv = g_wo[b * 256 + tid];
        skey[tid] = kv;
        float s = kv * kv;
#pragma unroll
        for (int o = 16; o > 0; o >>= 1) s += __shfl_down_sync(0xffffffffu, s, o);
        if (lane == 0) part[tid >> 5] = s;
    }
    __syncthreads();
    if (tid == 0) {
        s_knorm = fmaxf(sqrtf(part[0] + part[1]), EPSF);
        s_beta = softplusf(g_wo[b * 256 + 192]);
        s_ga = sigf(g_wo[b * 256 + 193]);
        s_gw = sigf(g_wo[b * 256 + 194]);
    }
    __syncthreads();

    const float4* mrow = (const float4*)(mem + ((size_t)b * NN + tid) * VV);
    float acc = 0.f, nrm = 0.f;
#pragma unroll
    for (int i = 0; i < 16; i++) {
        float4 m4 = mrow[i];
        acc += m4.x * skey[4 * i] + m4.y * skey[4 * i + 1] + m4.z * skey[4 * i + 2] + m4.w * skey[4 * i + 3];
        nrm += m4.x * m4.x + m4.y * m4.y + m4.z * m4.z + m4.w * m4.w;
    }
    float sim = s_beta * acc / (fmaxf(sqrtf(nrm), EPSF) * s_knorm);

    float v = sim;
#pragma unroll
    for (int o = 16; o > 0; o >>= 1) v = fmaxf(v, __shfl_down_sync(0xffffffffu, v, o));
    if (lane == 0) red[wid] = v;
    __syncthreads();
    if (tid == 0) {
        float m = red[0];
#pragma unroll
        for (int i = 1; i < 16; i++) m = fmaxf(m, red[i]);
        s_m = m;
    }
    __syncthreads();
    float e = expf(sim - s_m);
    v = e;
#pragma unroll
    for (int o = 16; o > 0; o >>= 1) v += __shfl_down_sync(0xffffffffu, v, o);
    if (lane == 0) red[wid] = v;
    __syncthreads();
    if (tid == 0) {
        float t = 0.f;
#pragma unroll
        for (int i = 0; i < 16; i++) t += red[i];
        s_sum = t;
    }
    __syncthreads();
    float cww = e / s_sum;

    float ww = s_gw * (s_ga * g_alloc[b * 512 + tid] + (1.f - s_ga) * cww);
    out[OUT_WW + b * 512 + tid] = ww;
    v = ww;
#pragma unroll
    for (int o = 16; o > 0; o >>= 1) v += __shfl_down_sync(0xffffffffu, v, o);
    if (lane == 0) red[wid] = v;
    __syncthreads();
    if (tid == 0) {
        float t = 0.f;
#pragma unroll
        for (int i = 0; i < 16; i++) t += red[i];
        s_ws = t;
    }
    __syncthreads();
    out[OUT_PREC + b * 512 + tid] = (1.f - s_ws) * prec[b * 512 + tid] + ww;
    float u = usage[b * 512 + tid], w0 = wwin[b * 512 + tid];
    out[OUT_USAGE + b * 512 + tid] = (u + w0 - u * w0) * g_psi[b * 512 + tid];
}

// ============================================================
// 6) fused memory + link update; link part tiled with smem wm/p staging
// ============================================================
__global__ void __launch_bounds__(256) k_memlink(const float* __restrict__ mem,
                                                 const float* __restrict__ link,
                                                 const float* __restrict__ prec,
                                                 float* __restrict__ out) {
    int bx = blockIdx.x;
    int tid = threadIdx.x;
    if (bx < 2048) {
        int gid = bx * 256 + tid;
        int v4 = gid & 15, n = (gid >> 4) & 511, b = gid >> 13;
        float4 m = ((const float4*)mem)[gid];
        float ww = out[OUT_WW + b * 512 + n];
        float4 er = ((const float4*)g_erase)[b * 16 + v4];
        float4 ad = ((const float4*)g_add)[b * 16 + v4];
        float4 r;
        r.x = m.x * (1.f - ww * er.x) + ww * ad.x;
        r.y = m.y * (1.f - ww * er.y) + ww * ad.y;
        r.z = m.z * (1.f - ww * er.z) + ww * ad.z;
        r.w = m.w * (1.f - ww * er.w) + ww * ad.w;
        __stwt(&((float4*)(out + OUT_MEM))[gid], r);
    } else {
        int idx = bx - 2048;
        int b = idx >> 5;
        int nt = idx & 31;
        int n0 = nt * 16;
        __shared__ __align__(16) float swm[512];
        __shared__ __align__(16) float spp[512];
        __shared__ float sww[16];
        if (tid < 128)
            ((float4*)swm)[tid] = ((const float4*)(out + OUT_WW + b * 512))[tid];
        else
            ((float4*)spp)[tid - 128] = ((const float4*)(prec + b * 512))[tid - 128];
        if (tid < 16) sww[tid] = out[OUT_WW + b * 512 + n0 + tid];
        __syncthreads();

        int mq = tid & 127;
        int nh = tid >> 7;
        int m0 = mq * 4;
        const float4* lbase = (const float4*)(link + (size_t)b * NN * NN);
        float4* obase = (float4*)(out + OUT_LINK + (size_t)b * NN * NN);
        float4 wm = *(const float4*)&swm[m0];
        float4 p  = *(const float4*)&spp[m0];
        float4 omm;
        omm.x = 1.f - wm.x; omm.y = 1.f - wm.y; omm.z = 1.f - wm.z; omm.w = 1.f - wm.w;
#pragma unroll
        for (int i = 0; i < 8; i++) {
            int n = n0 + i * 2 + nh;
            float wn = sww[i * 2 + nh];
            float om = 1.f - wn;
            float4 l = lbase[(size_t)n * 128 + mq];
            float4 r;
            r.x = om * omm.x * l.x + wn * p.x;
            r.y = om * omm.y * l.y + wn * p.y;
            r.z = om * omm.z * l.z + wn * p.z;
            r.w = om * omm.w * l.w + wn * p.w;
            if (m0 == n)     r.x = 0.f;
            if (m0 + 1 == n) r.y = 0.f;
            if (m0 + 2 == n) r.z = 0.f;
            if (m0 + 3 == n) r.w = 0.f;
            __stwt(&obase[(size_t)n * 128 + mq], r);
        }
    }
}

extern "C" void kernel_launch(void* const* d_in, const int* in_sizes, int n_in,
                              void* d_out, int out_size) {
    const float* x             = (const float*)d_in[0];
    const float* h             = (const float*)d_in[1];
    const float* c             = (const float*)d_in[2];
    const float* memory        = (const float*)d_in[3];
    const float* read_weights  = (const float*)d_in[4];
    const float* write_weights = (const float*)d_in[5];
    const float* usage         = (const float*)d_in[6];
    const float* link          = (const float*)d_in[7];
    const float* prec          = (const float*)d_in[8];
    const float* W_ih          = (const float*)d_in[9];
    const float* W_hh          = (const float*)d_in[10];
    const float* b_ih          = (const float*)d_in[11];
    const float* b_hh          = (const float*)d_in[12];
    const float* W_read        = (const float*)d_in[13];
    const float* b_read        = (const float*)d_in[14];
    const float* W_write       = (const float*)d_in[15];
    const float* b_write       = (const float*)d_in[16];
    const float* W_pol         = (const float*)d_in[17];
    const float* b_pol         = (const float*)d_in[18];
    const float* W_val         = (const float*)d_in[19];
    const float* b_val         = (const float*)d_in[20];
    float* out = (float*)d_out;

    k_big<<<832, 512>>>(memory, link, read_weights, h, W_read, b_read, usage);
    k_mix<<<64, 512>>>(memory, x, h, out);
    k_gates<<<dim3(64, 7), 256>>>(W_ih, W_hh);
    k_hout<<<dim3(64, 7), 512>>>(c, b_ih, b_hh, W_write, b_write, W_pol, b_pol, W_val, b_val, out);
    k_wall<<<64, 512>>>(memory, usage, write_weights, prec, out);
    k_memlink<<<4096, 256>>>(memory, link, prec, out);
}

// round 17
// speedup vs baseline: 1.2511x; 1.1489x over previous
#include <cuda_runtime.h>
#include <math.h>

#define BB 64
#define NN 512
#define VV 64
#define HH 512
#define RR 4
#define KK 32
#define EPSF 1e-8f

// output offsets (floats), tuple order:
// logits, value, h_new, c_new, mem_new, w_r, write_w, usage_new, link_new, prec_new
#define OUT_LOGITS 0
#define OUT_VALUE  1152
#define OUT_H      1216
#define OUT_C      33984
#define OUT_MEM    66752
#define OUT_WR     2163904
#define OUT_WW     2294976
#define OUT_USAGE  2327744
#define OUT_LINK   2360512
#define OUT_PREC   19137728

// workspace
__device__ __align__(16) float g_rpi[BB * RR * 3];
__device__ __align__(16) float g_cw[BB * RR * NN];
__device__ __align__(16) float g_fw[BB * RR * NN];
__device__ __align__(16) float g_bwp[8 * BB * RR * NN];
__device__ __align__(16) float g_psi[BB * NN];
__device__ __align__(16) float g_inT[896 * BB];
__device__ __align__(16) float g_gpart[7 * BB * 2048];
__device__ __align__(16) float g_wo[BB * 256];
__device__ __align__(16) float g_erase[BB * VV];
__device__ __align__(16) float g_add[BB * VV];
__device__ __align__(16) float g_alloc[BB * NN];

__device__ __forceinline__ float sigf(float x) { return 1.f / (1.f + expf(-x)); }
__device__ __forceinline__ float softplusf(float x) { return x > 20.f ? x : log1pf(expf(x)); }
__device__ __forceinline__ unsigned f2o(float f) {
    unsigned u = __float_as_uint(f);
    return (u & 0x80000000u) ? ~u : (u | 0x80000000u);
}

// ============================================================
// 1) mega-kernel: content (256) | fwbw single-pass pipelined (512) | alloc (64)
// ============================================================
__global__ void __launch_bounds__(512) k_big(const float* __restrict__ mem,
                                             const float* __restrict__ link,
                                             const float* __restrict__ rw,
                                             const float* __restrict__ h,
                                             const float* __restrict__ Wr,
                                             const float* __restrict__ br,
                                             const float* __restrict__ usage) {
    __shared__ __align__(16) float buf[10240];   // tile[8192] | srw[2048]
    int tid = threadIdx.x;
    int blk = blockIdx.x;

    if (blk < 256) {
        // ---------------- content per (b,r): inline read-projection ----------------
        int b = blk >> 2, r = blk & 3;
        float* hsh  = buf;
        float* rosh = buf + 512;
        float* red  = buf + 580;
        float* sc   = buf + 596;
        int lane = tid & 31, warp = tid >> 5;

        hsh[tid] = h[b * 512 + tid];
        __syncthreads();

        for (int row = warp; row < 68; row += 16) {
            const float4* w4 = (const float4*)(Wr + (size_t)(r * 68 + row) * HH);
            float a = 0.f;
#pragma unroll
            for (int i = 0; i < 4; i++) {
                float4 w = w4[lane + 32 * i];
                float4 hv = *(const float4*)&hsh[(lane + 32 * i) * 4];
                a += w.x * hv.x + w.y * hv.y + w.z * hv.z + w.w * hv.w;
            }
#pragma unroll
            for (int o = 16; o > 0; o >>= 1) a += __shfl_down_sync(0xffffffffu, a, o);
            if (lane == 0) rosh[row] = a + br[r * 68 + row];
        }
        __syncthreads();

        if (tid == 0) {
            sc[0] = softplusf(rosh[64]);
            float p0 = rosh[65], p1 = rosh[66], p2 = rosh[67];
            float mx = fmaxf(p0, fmaxf(p1, p2));
            float e0 = expf(p0 - mx), e1 = expf(p1 - mx), e2 = expf(p2 - mx);
            float inv = 1.f / (e0 + e1 + e2);
            g_rpi[(b * 4 + r) * 3 + 0] = e0 * inv;
            g_rpi[(b * 4 + r) * 3 + 1] = e1 * inv;
            g_rpi[(b * 4 + r) * 3 + 2] = e2 * inv;
        }
        if (tid < 32) {
            float v = rosh[tid] * rosh[tid] + rosh[tid + 32] * rosh[tid + 32];
#pragma unroll
            for (int o = 16; o > 0; o >>= 1) v += __shfl_down_sync(0xffffffffu, v, o);
            if (tid == 0) sc[1] = fmaxf(sqrtf(v), EPSF);
        }
        __syncthreads();

        const float4* mrow = (const float4*)(mem + ((size_t)b * NN + tid) * VV);
        float acc = 0.f, nrm = 0.f;
#pragma unroll
        for (int i = 0; i < 16; i++) {
            float4 m4 = mrow[i];
            acc += m4.x * rosh[4 * i] + m4.y * rosh[4 * i + 1] + m4.z * rosh[4 * i + 2] + m4.w * rosh[4 * i + 3];
            nrm += m4.x * m4.x + m4.y * m4.y + m4.z * m4.z + m4.w * m4.w;
        }
        float score = sc[0] * acc / (fmaxf(sqrtf(nrm), EPSF) * sc[1]);
        unsigned u = f2o(score);

        unsigned prefix = 0u;
#pragma unroll
        for (int bit = 31; bit >= 0; --bit) {
            unsigned cand = prefix | (1u << bit);
            int cnt = __syncthreads_count(u >= cand);
            if (cnt >= KK) prefix = cand;
        }

        float e = (u >= prefix) ? expf(score) : 0.f;
        float v = e;
#pragma unroll
        for (int o = 16; o > 0; o >>= 1) v += __shfl_down_sync(0xffffffffu, v, o);
        if (lane == 0) red[warp] = v;
        __syncthreads();
        if (tid == 0) {
            float t = 0.f;
#pragma unroll
            for (int i = 0; i < 16; i++) t += red[i];
            sc[2] = t;
        }
        __syncthreads();
        g_cw[(b * 4 + r) * 512 + tid] = e / sc[2];
    } else if (blk < 768) {
        // ---------------- fw + bw single pass, software-pipelined loads ----------
        int idx = blk - 256;
        int b = idx >> 3, mc = idx & 7;
        float* tile = buf;          // 16 x 512
        float* srw  = buf + 8192;   // 2048
        int lane = tid & 31, w = tid >> 5;

        ((float4*)srw)[tid] = ((const float4*)(rw + b * 2048))[tid];

        const float4* src0 = (const float4*)(link + ((size_t)b * NN + mc * 64) * NN);
        float4 p0 = src0[tid], p1 = src0[tid + 512], p2 = src0[tid + 1024], p3 = src0[tid + 1536];

        float a0 = 0.f, a1 = 0.f, a2 = 0.f, a3 = 0.f;
#pragma unroll
        for (int st = 0; st < 4; st++) {
            ((float4*)tile)[tid]        = p0;
            ((float4*)tile)[tid + 512]  = p1;
            ((float4*)tile)[tid + 1024] = p2;
            ((float4*)tile)[tid + 1536] = p3;
            __syncthreads();

            if (st < 3) {
                const float4* src = (const float4*)(link + ((size_t)b * NN + mc * 64 + (st + 1) * 16) * NN);
                p0 = src[tid]; p1 = src[tid + 512]; p2 = src[tid + 1024]; p3 = src[tid + 1536];
            }

            float f0 = 0.f, f1 = 0.f, f2 = 0.f, f3 = 0.f;
#pragma unroll
            for (int i = 0; i < 4; i++) {
                int cq = lane + 32 * i;
                float4 l = *(const float4*)&tile[w * 512 + cq * 4];
                float4 w0 = *(const float4*)&srw[cq * 4];
                float4 w1 = *(const float4*)&srw[512 + cq * 4];
                float4 w2 = *(const float4*)&srw[1024 + cq * 4];
                float4 w3 = *(const float4*)&srw[1536 + cq * 4];
                f0 += l.x * w0.x + l.y * w0.y + l.z * w0.z + l.w * w0.w;
                f1 += l.x * w1.x + l.y * w1.y + l.z * w1.z + l.w * w1.w;
                f2 += l.x * w2.x + l.y * w2.y + l.z * w2.z + l.w * w2.w;
                f3 += l.x * w3.x + l.y * w3.y + l.z * w3.z + l.w * w3.w;
            }
#pragma unroll
            for (int o = 16; o > 0; o >>= 1) {
                f0 += __shfl_down_sync(0xffffffffu, f0, o);
                f1 += __shfl_down_sync(0xffffffffu, f1, o);
                f2 += __shfl_down_sync(0xffffffffu, f2, o);
                f3 += __shfl_down_sync(0xffffffffu, f3, o);
            }
            if (lane == 0) {
                int n = mc * 64 + st * 16 + w;
                g_fw[(b * 4 + 0) * 512 + n] = f0;
                g_fw[(b * 4 + 1) * 512 + n] = f1;
                g_fw[(b * 4 + 2) * 512 + n] = f2;
                g_fw[(b * 4 + 3) * 512 + n] = f3;
            }

#pragma unroll
            for (int m = 0; m < 16; m++) {
                float l = tile[m * 512 + tid];
                int gm = mc * 64 + st * 16 + m;
                a0 += l * srw[gm];
                a1 += l * srw[512 + gm];
                a2 += l * srw[1024 + gm];
                a3 += l * srw[1536 + gm];
            }
            __syncthreads();
        }
        size_t base = (((size_t)mc * 64 + b) * 4) * 512 + tid;
        g_bwp[base]        = a0;
        g_bwp[base + 512]  = a1;
        g_bwp[base + 1024] = a2;
        g_bwp[base + 1536] = a3;
    } else {
        // ---------------- allocation per b: barrier-free selection product ----------
        int b = blk - 768;
        buf[tid] = usage[b * 512 + tid];
        __syncthreads();
        float un = buf[tid];
        float prod = 1.f;
#pragma unroll 8
        for (int m = 0; m < 512; m++) {
            float um = buf[m];
            bool before = (um < un) || (um == un && m < tid);
            prod *= before ? um : 1.f;
        }
        g_alloc[b * 512 + tid] = (1.f - un) * prod;
    }
}

// ============================================================
// 2) fused per-b: w_r mix + psi + rvec (single memory pass) + pack inT
// ============================================================
__global__ void __launch_bounds__(512) k_mix(const float* __restrict__ mem,
                                             const float* __restrict__ x,
                                             const float* __restrict__ h,
                                             float* __restrict__ out) {
    int b = blockIdx.x, tid = threadIdx.x;
    __shared__ float swr[4][512];
    __shared__ float spart[8][4][64];
    __shared__ float srv[256];
    int n = tid;
    float psi = 1.f;
#pragma unroll
    for (int r = 0; r < 4; r++) {
        int o = (b * 4 + r) * 512 + n;
        float bwv = 0.f;
#pragma unroll
        for (int mc = 0; mc < 8; mc++)
            bwv += g_bwp[((size_t)(mc * 64 + b) * 4 + r) * 512 + n];
        float p0 = g_rpi[(b * 4 + r) * 3 + 0];
        float p1 = g_rpi[(b * 4 + r) * 3 + 1];
        float p2 = g_rpi[(b * 4 + r) * 3 + 2];
        float wr = p0 * bwv + p1 * g_cw[o] + p2 * g_fw[o];
        swr[r][n] = wr;
        out[OUT_WR + o] = wr;
        psi *= (1.f - wr);
    }
    g_psi[b * 512 + n] = psi;
    __syncthreads();

    // rvec: one pass over memory; thread = (oct of 64 n, v)
    int oct = tid >> 6, v = tid & 63;
    const float* mp = mem + (size_t)b * NN * VV + (size_t)(oct * 64) * 64 + v;
    float ac0 = 0.f, ac1 = 0.f, ac2 = 0.f, ac3 = 0.f;
#pragma unroll 4
    for (int i = 0; i < 64; i++) {
        float m = mp[(size_t)i * 64];
        int nn = oct * 64 + i;
        ac0 += swr[0][nn] * m;
        ac1 += swr[1][nn] * m;
        ac2 += swr[2][nn] * m;
        ac3 += swr[3][nn] * m;
    }
    spart[oct][0][v] = ac0;
    spart[oct][1][v] = ac1;
    spart[oct][2][v] = ac2;
    spart[oct][3][v] = ac3;
    __syncthreads();
    if (tid < 256) {
        int r = tid >> 6, vv = tid & 63;
        float s = 0.f;
#pragma unroll
        for (int o = 0; o < 8; o++) s += spart[o][r][vv];
        srv[tid] = s;
    }
    __syncthreads();

    for (int k = tid; k < 896; k += 512) {
        float val;
        if (k < 128) val = x[b * 128 + k];
        else if (k < 384) val = srv[k - 128];
        else val = h[b * 512 + (k - 384)];
        g_inT[k * 64 + b] = val;
    }
}

// ============================================================
// 3) gates GEMM: (64b x 2048j), K=896 = 7 splits of 128; j-tile 32
// ============================================================
__global__ void __launch_bounds__(256) k_gates(const float* __restrict__ Wih,
                                               const float* __restrict__ Whh) {
    __shared__ __align__(16) float Wt[32][34];
    __shared__ __align__(16) float It[32][68];
    int tid = threadIdx.x;
    int ks = blockIdx.y;
    int koff = ks * 128;
    int j0 = blockIdx.x * 32;
    int tx = tid & 15, ty = tid >> 4;
    int jj = tid >> 3, kq = tid & 7;
    float acc[2][4];
#pragma unroll
    for (int i = 0; i < 2; i++)
#pragma unroll
        for (int j = 0; j < 4; j++) acc[i][j] = 0.f;

    for (int kst = 0; kst < 128; kst += 32) {
        int vk = koff + kst + kq * 4;
        const float* wp = (vk < 384) ? (Wih + (size_t)(j0 + jj) * 384 + vk)
                                     : (Whh + (size_t)(j0 + jj) * 512 + (vk - 384));
        float4 wv = *(const float4*)wp;
        Wt[kq * 4 + 0][jj] = wv.x;
        Wt[kq * 4 + 1][jj] = wv.y;
        Wt[kq * 4 + 2][jj] = wv.z;
        Wt[kq * 4 + 3][jj] = wv.w;
        *(float4*)&It[ty][tx * 4]      = *(const float4*)&g_inT[(koff + kst + ty) * 64 + tx * 4];
        *(float4*)&It[ty + 16][tx * 4] = *(const float4*)&g_inT[(koff + kst + ty + 16) * 64 + tx * 4];
        __syncthreads();
#pragma unroll
        for (int kk = 0; kk < 32; kk++) {
            float4 av = *(float4*)&It[kk][tx * 4];
            float2 wv2 = *(float2*)&Wt[kk][ty * 2];
            acc[0][0] += wv2.x * av.x; acc[0][1] += wv2.x * av.y; acc[0][2] += wv2.x * av.z; acc[0][3] += wv2.x * av.w;
            acc[1][0] += wv2.y * av.x; acc[1][1] += wv2.y * av.y; acc[1][2] += wv2.y * av.z; acc[1][3] += wv2.y * av.w;
        }
        __syncthreads();
    }
#pragma unroll
    for (int jq = 0; jq < 2; jq++)
#pragma unroll
        for (int bq = 0; bq < 4; bq++)
            g_gpart[(((size_t)ks * 64 + (tx * 4 + bq)) * 2048) + j0 + ty * 2 + jq] = acc[jq][bq];
}

// ============================================================
// 4) LSTM + projections, parallel over (b, 7 row-chunks)
// ============================================================
__global__ void __launch_bounds__(512) k_hout(
    const float* __restrict__ c, const float* __restrict__ bih, const float* __restrict__ bhh,
    const float* __restrict__ Ww, const float* __restrict__ bw_,
    const float* __restrict__ Wp, const float* __restrict__ bp,
    const float* __restrict__ Wv, const float* __restrict__ bv,
    float* __restrict__ out) {
    int b = blockIdx.x, pc = blockIdx.y, tid = threadIdx.x;
    __shared__ __align__(16) float sh[512];
    int lane = tid & 31, wid = tid >> 5;

    float gi = bih[tid] + bhh[tid];
    float gf = bih[512 + tid] + bhh[512 + tid];
    float gg = bih[1024 + tid] + bhh[1024 + tid];
    float go = bih[1536 + tid] + bhh[1536 + tid];
#pragma unroll
    for (int ks = 0; ks < 7; ks++) {
        const float* gp = g_gpart + ((size_t)(ks * 64 + b) * 2048);
        gi += gp[tid];
        gf += gp[512 + tid];
        gg += gp[1024 + tid];
        go += gp[1536 + tid];
    }
    float cn = sigf(gf) * c[b * 512 + tid] + sigf(gi) * tanhf(gg);
    float hn = sigf(go) * tanhf(cn);
    if (pc == 0) {
        out[OUT_C + b * 512 + tid] = cn;
        out[OUT_H + b * 512 + tid] = hn;
    }
    sh[tid] = hn;
    __syncthreads();

#pragma unroll
    for (int rr = 0; rr < 2; rr++) {
        int ro = wid + rr * 16;
        int row = pc * 31 + ro;
        if (ro < 31 && row < 214) {
            const float* wrow;
            float bias;
            if (row < 195)      { wrow = Ww + row * 512;         bias = bw_[row]; }
            else if (row < 213) { wrow = Wp + (row - 195) * 512; bias = bp[row - 195]; }
            else                { wrow = Wv;                     bias = bv[0]; }
            const float4* w4 = (const float4*)wrow;
            float acc = 0.f;
#pragma unroll
            for (int i = 0; i < 4; i++) {
                float4 wv = w4[lane + 32 * i];
                float4 hv = *(const float4*)&sh[(lane + 32 * i) * 4];
                acc += wv.x * hv.x + wv.y * hv.y + wv.z * hv.z + wv.w * hv.w;
            }
#pragma unroll
            for (int o = 16; o > 0; o >>= 1) acc += __shfl_down_sync(0xffffffffu, acc, o);
            if (lane == 0) {
                acc += bias;
                if (row < 64)       g_wo[b * 256 + row] = acc;
                else if (row < 128) g_erase[b * 64 + (row - 64)] = sigf(acc);
                else if (row < 192) g_add[b * 64 + (row - 128)] = tanhf(acc);
                else if (row < 195) g_wo[b * 256 + row] = acc;
                else if (row < 213) out[OUT_LOGITS + b * 18 + (row - 195)] = acc;
                else                out[OUT_VALUE + b] = acc;
            }
        }
    }
}

// ============================================================
// 5) per-b write path (short)
// ============================================================
__global__ void __launch_bounds__(512) k_wall(
    const float* __restrict__ mem, const float* __restrict__ usage,
    const float* __restrict__ wwin, const float* __restrict__ prec,
    float* __restrict__ out) {
    int b = blockIdx.x, tid = threadIdx.x;
    __shared__ __align__(16) float skey[64];
    __shared__ float red[16];
    __shared__ float part[2];
    __shared__ float s_beta, s_knorm, s_ga, s_gw, s_m, s_sum, s_ws;
    int lane = tid & 31, wid = tid >> 5;

    if (tid < 64) {
        float kv = g_wo[b * 256 + tid];
        skey[tid] = kv;
        float s = kv * kv;
#pragma unroll
        for (int o = 16; o > 0; o >>= 1) s += __shfl_down_sync(0xffffffffu, s, o);
        if (lane == 0) part[tid >> 5] = s;
    }
    __syncthreads();
    if (tid == 0) {
        s_knorm = fmaxf(sqrtf(part[0] + part[1]), EPSF);
        s_beta = softplusf(g_wo[b * 256 + 192]);
        s_ga = sigf(g_wo[b * 256 + 193]);
        s_gw = sigf(g_wo[b * 256 + 194]);
    }
    __syncthreads();

    const float4* mrow = (const float4*)(mem + ((size_t)b * NN + tid) * VV);
    float acc = 0.f, nrm = 0.f;
#pragma unroll
    for (int i = 0; i < 16; i++) {
        float4 m4 = mrow[i];
        acc += m4.x * skey[4 * i] + m4.y * skey[4 * i + 1] + m4.z * skey[4 * i + 2] + m4.w * skey[4 * i + 3];
        nrm += m4.x * m4.x + m4.y * m4.y + m4.z * m4.z + m4.w * m4.w;
    }
    float sim = s_beta * acc / (fmaxf(sqrtf(nrm), EPSF) * s_knorm);

    float v = sim;
#pragma unroll
    for (int o = 16; o > 0; o >>= 1) v = fmaxf(v, __shfl_down_sync(0xffffffffu, v, o));
    if (lane == 0) red[wid] = v;
    __syncthreads();
    if (tid == 0) {
        float m = red[0];
#pragma unroll
        for (int i = 1; i < 16; i++) m = fmaxf(m, red[i]);
        s_m = m;
    }
    __syncthreads();
    float e = expf(sim - s_m);
    v = e;
#pragma unroll
    for (int o = 16; o > 0; o >>= 1) v += __shfl_down_sync(0xffffffffu, v, o);
    if (lane == 0) red[wid] = v;
    __syncthreads();
    if (tid == 0) {
        float t = 0.f;
#pragma unroll
        for (int i = 0; i < 16; i++) t += red[i];
        s_sum = t;
    }
    __syncthreads();
    float cww = e / s_sum;

    float ww = s_gw * (s_ga * g_alloc[b * 512 + tid] + (1.f - s_ga) * cww);
    out[OUT_WW + b * 512 + tid] = ww;
    v = ww;
#pragma unroll
    for (int o = 16; o > 0; o >>= 1) v += __shfl_down_sync(0xffffffffu, v, o);
    if (lane == 0) red[wid] = v;
    __syncthreads();
    if (tid == 0) {
        float t = 0.f;
#pragma unroll
        for (int i = 0; i < 16; i++) t += red[i];
        s_ws = t;
    }
    __syncthreads();
    out[OUT_PREC + b * 512 + tid] = (1.f - s_ws) * prec[b * 512 + tid] + ww;
    float u = usage[b * 512 + tid], w0 = wwin[b * 512 + tid];
    out[OUT_USAGE + b * 512 + tid] = (u + w0 - u * w0) * g_psi[b * 512 + tid];
}

// ============================================================
// 6) fused memory + link update; link part tiled with smem wm/p staging
// ============================================================
__global__ void __launch_bounds__(256) k_memlink(const float* __restrict__ mem,
                                                 const float* __restrict__ link,
                                                 const float* __restrict__ prec,
                                                 float* __restrict__ out) {
    int bx = blockIdx.x;
    int tid = threadIdx.x;
    if (bx < 2048) {
        int gid = bx * 256 + tid;
        int v4 = gid & 15, n = (gid >> 4) & 511, b = gid >> 13;
        float4 m = ((const float4*)mem)[gid];
        float ww = out[OUT_WW + b * 512 + n];
        float4 er = ((const float4*)g_erase)[b * 16 + v4];
        float4 ad = ((const float4*)g_add)[b * 16 + v4];
        float4 r;
        r.x = m.x * (1.f - ww * er.x) + ww * ad.x;
        r.y = m.y * (1.f - ww * er.y) + ww * ad.y;
        r.z = m.z * (1.f - ww * er.z) + ww * ad.z;
        r.w = m.w * (1.f - ww * er.w) + ww * ad.w;
        __stwt(&((float4*)(out + OUT_MEM))[gid], r);
    } else {
        int idx = bx - 2048;
        int b = idx >> 5;
        int nt = idx & 31;
        int n0 = nt * 16;
        __shared__ __align__(16) float swm[512];
        __shared__ __align__(16) float spp[512];
        __shared__ float sww[16];
        if (tid < 128)
            ((float4*)swm)[tid] = ((const float4*)(out + OUT_WW + b * 512))[tid];
        else
            ((float4*)spp)[tid - 128] = ((const float4*)(prec + b * 512))[tid - 128];
        if (tid < 16) sww[tid] = out[OUT_WW + b * 512 + n0 + tid];
        __syncthreads();

        int mq = tid & 127;
        int nh = tid >> 7;
        int m0 = mq * 4;
        const float4* lbase = (const float4*)(link + (size_t)b * NN * NN);
        float4* obase = (float4*)(out + OUT_LINK + (size_t)b * NN * NN);
        float4 wm = *(const float4*)&swm[m0];
        float4 p  = *(const float4*)&spp[m0];
        float4 omm;
        omm.x = 1.f - wm.x; omm.y = 1.f - wm.y; omm.z = 1.f - wm.z; omm.w = 1.f - wm.w;
#pragma unroll
        for (int i = 0; i < 8; i++) {
            int n = n0 + i * 2 + nh;
            float wn = sww[i * 2 + nh];
            float om = 1.f - wn;
            float4 l = lbase[(size_t)n * 128 + mq];
            float4 r;
            r.x = om * omm.x * l.x + wn * p.x;
            r.y = om * omm.y * l.y + wn * p.y;
            r.z = om * omm.z * l.z + wn * p.z;
            r.w = om * omm.w * l.w + wn * p.w;
            if (m0 == n)     r.x = 0.f;
            if (m0 + 1 == n) r.y = 0.f;
            if (m0 + 2 == n) r.z = 0.f;
            if (m0 + 3 == n) r.w = 0.f;
            __stwt(&obase[(size_t)n * 128 + mq], r);
        }
    }
}

extern "C" void kernel_launch(void* const* d_in, const int* in_sizes, int n_in,
                              void* d_out, int out_size) {
    const float* x             = (const float*)d_in[0];
    const float* h             = (const float*)d_in[1];
    const float* c             = (const float*)d_in[2];
    const float* memory        = (const float*)d_in[3];
    const float* read_weights  = (const float*)d_in[4];
    const float* write_weights = (const float*)d_in[5];
    const float* usage         = (const float*)d_in[6];
    const float* link          = (const float*)d_in[7];
    const float* prec          = (const float*)d_in[8];
    const float* W_ih          = (const float*)d_in[9];
    const float* W_hh          = (const float*)d_in[10];
    const float* b_ih          = (const float*)d_in[11];
    const float* b_hh          = (const float*)d_in[12];
    const float* W_read        = (const float*)d_in[13];
    const float* b_read        = (const float*)d_in[14];
    const float* W_write       = (const float*)d_in[15];
    const float* b_write       = (const float*)d_in[16];
    const float* W_pol         = (const float*)d_in[17];
    const float* b_pol         = (const float*)d_in[18];
    const float* W_val         = (const float*)d_in[19];
    const float* b_val         = (const float*)d_in[20];
    float* out = (float*)d_out;

    k_big<<<832, 512>>>(memory, link, read_weights, h, W_read, b_read, usage);
    k_mix<<<64, 512>>>(memory, x, h, out);
    k_gates<<<dim3(64, 7), 256>>>(W_ih, W_hh);
    k_hout<<<dim3(64, 7), 512>>>(c, b_ih, b_hh, W_write, b_write, W_pol, b_pol, W_val, b_val, out);
    k_wall<<<64, 512>>>(memory, usage, write_weights, prec, out);
    k_memlink<<<4096, 256>>>(memory, link, prec, out);
}